// round 4
// baseline (speedup 1.0000x reference)
#include <cuda_runtime.h>
#include <cstdint>
#include <math.h>

#define HB 1024     // K
#define HM 8192     // M
#define RN 735      // true N
#define RNP 768     // padded N
#define YLD 768
#define NOUT 57
#define OUTPP (NOUT*NOUT)

#define KTILE 32
#define STAGES 3
#define KITERS (HB/KTILE)          // 32
#define TILE_B (128*KTILE*4)       // 16 KB
#define STAGE_B (2*TILE_B)         // 32 KB
#define SMEM_B (STAGES*STAGE_B)    // 96 KB

// Scratch (device globals; no allocation)
__device__ __align__(16) float g_A[RNP*HB];             // 3 MB (k-permuted, tf32)
__device__ __align__(16) float g_Wp[(size_t)HM*HB];     // 32 MB (k-permuted, tf32)
__device__ __align__(16) float g_Y[(size_t)HM*YLD];     // 25 MB
__device__ int g_tab[OUTPP];                            // gather table

// ---------------- helpers ----------------
__device__ __forceinline__ float to_tf32(float x) {
    float r; asm("cvt.rna.tf32.f32 %0, %1;" : "=f"(r) : "f"(x)); return r;
}
__device__ __forceinline__ uint32_t smem_u32(const void* p) {
    uint32_t a;
    asm("{ .reg .u64 t; cvta.to.shared.u64 t, %1; cvt.u32.u64 %0, t; }" : "=r"(a) : "l"(p));
    return a;
}
#define SWZ(o) ((o) ^ (((o) >> 3) & 0x70))
__device__ __forceinline__ void cp_async16(uint32_t dst, const void* src) {
    asm volatile("cp.async.cg.shared.global [%0], [%1], 16;" :: "r"(dst), "l"(src));
}
#define CP_COMMIT() asm volatile("cp.async.commit_group;" ::: "memory")
#define CP_WAIT1()  asm volatile("cp.async.wait_group 1;" ::: "memory")

// pair-interleave permutation within each 8-float k-group:
__device__ __forceinline__ int permdst(int k) {
    int c = k & ~7, kk = k & 7;
    return c + ((kk < 4) ? (kk * 2) : ((kk - 4) * 2 + 1));
}

// ---------------------------------------------------------------------------
// Kernel 1: A[r,h] = (sigmoid(te)+1)*relu(mat), tf32-rounded, k-permuted.
// ---------------------------------------------------------------------------
__global__ void prep_kernel(const float* __restrict__ mat,
                            const float* __restrict__ te) {
    int idx = blockIdx.x * blockDim.x + threadIdx.x;
    if (idx >= RNP * HB) return;
    int r = idx >> 10;
    int h = idx & 1023;
    float v = 0.0f;
    if (r < RN) {
        int t = r / 49;
        int rem = r % 49;
        int m = rem / 7;
        int n = rem % 7;
        float tev = te[h * 15 + t];
        float s = 1.0f / (1.0f + expf(-tev)) + 1.0f;
        float mv = mat[h * 49 + n * 7 + m];
        v = to_tf32(s * fmaxf(mv, 0.0f));
    }
    g_A[(r << 10) + permdst(h)] = v;
}

// ---------------------------------------------------------------------------
// Kernel 2: W -> g_Wp, tf32-rounded, k-permuted.
// ---------------------------------------------------------------------------
__global__ void permw_kernel(const float* __restrict__ W) {
    int gid = blockIdx.x * blockDim.x + threadIdx.x;
    if (gid >= (HM * HB) / 8) return;
    const float4* src = (const float4*)(W + (size_t)gid * 8);
    float4 x = src[0], y = src[1];
    float v0 = to_tf32(x.x), v1 = to_tf32(x.y), v2 = to_tf32(x.z), v3 = to_tf32(x.w);
    float v4 = to_tf32(y.x), v5 = to_tf32(y.y), v6 = to_tf32(y.z), v7 = to_tf32(y.w);
    float4* dst = (float4*)(g_Wp + (size_t)gid * 8);
    dst[0] = make_float4(v0, v4, v1, v5);
    dst[1] = make_float4(v2, v6, v3, v7);
}

// ---------------------------------------------------------------------------
// Kernel 2b: gather table.  entry = src(16b) | r(6b)<<16 | c(6b)<<22
// src: 0..734 = index into y-row; 0x8000 = const 1; 0x8001 = const 0
// ---------------------------------------------------------------------------
__global__ void table_kernel() {
    int idx = blockIdx.x * blockDim.x + threadIdx.x;
    if (idx >= OUTPP) return;
    int r = idx / NOUT;
    int c = idx - r * NOUT;
    int src;
    if (r == 0) {
        src = (c % 7 == 0) ? 0x8000 : 0x8001;
    } else if (c == 0) {
        src = (r % 7 == 0) ? 0x8000 : 0x8001;
    } else {
        int rr = r - 1;
        int s = rr / 7;
        int q = rr - s * 7;
        src = (7 * (7 - s) + (c - 1)) * 7 + q;
    }
    g_tab[idx] = src | (r << 16) | (c << 22);
}

// ---------------------------------------------------------------------------
// Kernel 3: tf32 mma.sync GEMM, restructured pipeline (1 sync/iter,
// loads issued before compute, uniform commit).
// ---------------------------------------------------------------------------
__global__ void __launch_bounds__(256, 2)
gemm_mma(const float* __restrict__ bias) {
    extern __shared__ char smem[];
    uint32_t sb = smem_u32(smem);

    int tid = threadIdx.x, lane = tid & 31, warp = tid >> 5;
    int g = lane >> 2, tg = lane & 3;
    int wm = warp >> 2, wn = warp & 3;
    int jBase = blockIdx.y * 128;
    int rBase = blockIdx.x * 128;

    const float* wsrc = g_Wp + (size_t)jBase * HB;
    const float* asrc = g_A + (size_t)rBase * HB;
    int lrow = tid >> 1, lhalf = tid & 1;

    float acc[4][4][4];
    #pragma unroll
    for (int mt = 0; mt < 4; mt++)
        #pragma unroll
        for (int nt = 0; nt < 4; nt++)
            #pragma unroll
            for (int i = 0; i < 4; i++) acc[mt][nt][i] = 0.f;

    auto load_stage = [&](int it) {
        int s = it % STAGES;
        int k0 = it * KTILE;
        uint32_t wd = sb + s * STAGE_B;
        uint32_t ad = wd + TILE_B;
        const float* wp = wsrc + (size_t)lrow * HB + k0 + lhalf * 16;
        const float* ap = asrc + (size_t)lrow * HB + k0 + lhalf * 16;
        #pragma unroll
        for (int c = 0; c < 4; c++) {
            uint32_t off = SWZ((uint32_t)(lrow * 128 + lhalf * 64 + c * 16));
            cp_async16(wd + off, wp + c * 4);
            cp_async16(ad + off, ap + c * 4);
        }
    };

    load_stage(0); CP_COMMIT();
    load_stage(1); CP_COMMIT();

    for (int it = 0; it < KITERS; it++) {
        CP_WAIT1();                 // stage `it` resident
        __syncthreads();            // also protects slot (it-1)%3 for reuse
        if (it + 2 < KITERS) load_stage(it + 2);
        CP_COMMIT();                // uniform group count

        int s = it % STAGES;
        const char* wb = smem + s * STAGE_B;
        const char* ab = wb + TILE_B;

        #pragma unroll
        for (int ks = 0; ks < 4; ks++) {
            uint32_t a0[4], a1[4], a2[4], a3[4];
            #pragma unroll
            for (int mt = 0; mt < 4; mt++) {
                int r0 = wm * 64 + mt * 16 + g;
                float2 lo = *(const float2*)(wb + SWZ((uint32_t)(r0 * 128 + ks * 32 + tg * 8)));
                float2 hi = *(const float2*)(wb + SWZ((uint32_t)((r0 + 8) * 128 + ks * 32 + tg * 8)));
                a0[mt] = __float_as_uint(lo.x);
                a2[mt] = __float_as_uint(lo.y);
                a1[mt] = __float_as_uint(hi.x);
                a3[mt] = __float_as_uint(hi.y);
            }
            #pragma unroll
            for (int nt = 0; nt < 4; nt++) {
                int rn_ = wn * 32 + nt * 8 + g;
                float2 bv = *(const float2*)(ab + SWZ((uint32_t)(rn_ * 128 + ks * 32 + tg * 8)));
                uint32_t b0 = __float_as_uint(bv.x);
                uint32_t b1 = __float_as_uint(bv.y);
                #pragma unroll
                for (int mt = 0; mt < 4; mt++) {
                    asm volatile(
                        "mma.sync.aligned.m16n8k8.row.col.f32.tf32.tf32.f32 "
                        "{%0,%1,%2,%3}, {%4,%5,%6,%7}, {%8,%9}, {%0,%1,%2,%3};"
                        : "+f"(acc[mt][nt][0]), "+f"(acc[mt][nt][1]),
                          "+f"(acc[mt][nt][2]), "+f"(acc[mt][nt][3])
                        : "r"(a0[mt]), "r"(a1[mt]), "r"(a2[mt]), "r"(a3[mt]),
                          "r"(b0), "r"(b1));
                }
            }
        }
    }

    // epilogue: bias + relu
    #pragma unroll
    for (int mt = 0; mt < 4; mt++) {
        int r0 = jBase + wm * 64 + mt * 16 + g;
        float bv0 = bias[r0], bv1 = bias[r0 + 8];
        float* y0 = g_Y + (size_t)r0 * YLD + rBase + wn * 32;
        float* y1 = g_Y + (size_t)(r0 + 8) * YLD + rBase + wn * 32;
        #pragma unroll
        for (int nt = 0; nt < 4; nt++) {
            float2 v0, v1;
            v0.x = fmaxf(acc[mt][nt][0] + bv0, 0.f);
            v0.y = fmaxf(acc[mt][nt][1] + bv0, 0.f);
            v1.x = fmaxf(acc[mt][nt][2] + bv1, 0.f);
            v1.y = fmaxf(acc[mt][nt][3] + bv1, 0.f);
            *(float2*)(y0 + nt * 8 + tg * 2) = v0;
            *(float2*)(y1 + nt * 8 + tg * 2) = v1;
        }
    }
}

// ---------------------------------------------------------------------------
// Kernel 4: assemble + normalize, table-driven, 4 j's per block.
// ---------------------------------------------------------------------------
#define JPB 4
__global__ void __launch_bounds__(256)
assemble_kernel(float* __restrict__ out) {
    __shared__ int   gt[OUTPP];          // 13 KB
    __shared__ float ys[JPB][RN + 1];
    __shared__ float dsh[JPB][NOUT + 1];
    int tid = threadIdx.x;
    int j0 = blockIdx.x * JPB;

    for (int i = tid; i < OUTPP; i += 256) gt[i] = g_tab[i];
    #pragma unroll
    for (int jj = 0; jj < JPB; jj++) {
        const float* yrow = &g_Y[(size_t)(j0 + jj) * YLD];
        for (int i = tid; i < RN; i += 256) ys[jj][i] = yrow[i];
    }
    __syncthreads();

    if (tid < JPB * NOUT) {
        int jj = tid / NOUT;
        int rr0 = tid - jj * NOUT;
        float sum;
        if (rr0 == 0) {
            sum = 9.0f;
        } else {
            int rr = rr0 - 1;
            int s = rr / 7;
            int q = rr - s * 7;
            sum = (q == 6) ? 1.0f : 0.0f;
            int pbase = 7 * (7 - s);
            #pragma unroll 8
            for (int k = 0; k < 56; k++)
                sum += ys[jj][(pbase + k) * 7 + q];
        }
        dsh[jj][rr0] = rsqrtf(fmaxf(sum, 1.0f));
    }
    __syncthreads();

    #pragma unroll
    for (int jj = 0; jj < JPB; jj++) {
        float* o = out + (size_t)(j0 + jj) * OUTPP;
        for (int idx = tid; idx < OUTPP; idx += 256) {
            int t = gt[idx];
            int src = t & 0xFFFF;
            int r = (t >> 16) & 0x3F;
            int c = (t >> 22) & 0x3F;
            float v;
            if (src < 0x8000) v = ys[jj][src];
            else              v = (src == 0x8000) ? 1.0f : 0.0f;
            o[idx] = v * dsh[jj][r] * dsh[jj][c];
        }
    }
}

// ---------------------------------------------------------------------------
extern "C" void kernel_launch(void* const* d_in, const int* in_sizes, int n_in,
                              void* d_out, int out_size) {
    const float* mat = (const float*)d_in[0];
    const float* te  = (const float*)d_in[1];
    const float* W   = (const float*)d_in[2];
    const float* b   = (const float*)d_in[3];
    float* out = (float*)d_out;

    static bool attr_set = false;
    if (!attr_set) {
        cudaFuncSetAttribute(gemm_mma, cudaFuncAttributeMaxDynamicSharedMemorySize,
                             SMEM_B);
        attr_set = true;
    }

    prep_kernel<<<(RNP * HB + 255) / 256, 256>>>(mat, te);
    permw_kernel<<<(HM * HB / 8 + 255) / 256, 256>>>(W);
    table_kernel<<<(OUTPP + 255) / 256, 256>>>();

    dim3 g(RNP / 128, HM / 128);   // (6, 64)
    gemm_mma<<<g, 256, SMEM_B>>>(b);

    assemble_kernel<<<HM / JPB, 256>>>(out);
}